// round 4
// baseline (speedup 1.0000x reference)
#include <cuda_runtime.h>

#define NN   50000
#define EE   800000
#define ETOT 850000
#define GG   256

// ---------------- scratch (device globals; no allocation allowed) ----------------
__device__ float g_xl1[NN * 128];
__device__ float g_xr1[NN * 128];
__device__ float g_out1[NN * 128];
__device__ float g_lg1[ETOT * 2];
__device__ float g_mx1[NN * 2];
__device__ float g_dn1[NN * 2];

__device__ float g_xl2[NN * 64];
__device__ float g_xr2[NN * 64];
__device__ float g_out2[NN * 64];
__device__ float g_lg2[ETOT];
__device__ float g_mx2[NN];
__device__ float g_dn2[NN];

__device__ float g_pool[GG * 64];
__device__ float g_cnt[GG];

__device__ __forceinline__ float lrelu(float v, float s) { return v > 0.f ? v : v * s; }

// float atomic-max via sign-split (valid with -inf init, no NaNs in logits)
__device__ __forceinline__ void atomicMaxF(float* a, float v) {
    if (v >= 0.f) atomicMax((int*)a, __float_as_int(v));
    else          atomicMin((unsigned int*)a, __float_as_uint(v));
}

// ---------------- init: zero accumulators, -inf maxima ----------------
__global__ void k_init() {
    int i = blockIdx.x * blockDim.x + threadIdx.x;
    const float ninf = __int_as_float(0xff800000);
    if (i < NN * 128) g_out1[i] = 0.f;
    if (i < NN * 64)  g_out2[i] = 0.f;
    if (i < NN * 2) { g_dn1[i] = 0.f; g_mx1[i] = ninf; }
    if (i < NN)     { g_dn2[i] = 0.f; g_mx2[i] = ninf; }
    if (i < GG * 64) g_pool[i] = 0.f;
    if (i < GG)      g_cnt[i] = 0.f;
}

// ---------------- layer-1 node transforms: xl1/xr1 = x @ w^T + b ----------------
__global__ void k_gemm1(const float* __restrict__ x,
                        const float* __restrict__ wl, const float* __restrict__ bl,
                        const float* __restrict__ wr, const float* __restrict__ br) {
    extern __shared__ float sm[];
    float* sw = sm;                 // 2 * 128 * 132 floats
    float* sx = sm + 2 * 128 * 132; // 8 * 128 floats
    int t = threadIdx.x;

    for (int idx = t; idx < 128 * 32; idx += 256) {
        int j = idx >> 5, k4 = (idx & 31) << 2;
        *(float4*)(sw + j * 132 + k4)             = *(const float4*)(wl + j * 128 + k4);
        *(float4*)(sw + 128 * 132 + j * 132 + k4) = *(const float4*)(wr + j * 128 + k4);
    }
    __syncthreads();

    int half = t >> 7;
    int j    = t & 127;
    const float* wrow = sw + half * 128 * 132 + j * 132;
    float bias = half ? br[j] : bl[j];
    float* outbase = half ? g_xr1 : g_xl1;
    int node0 = blockIdx.x * 128;

    for (int gr = 0; gr < 16; gr++) {
        int nb = node0 + gr * 8;
        {   // stage 8 x-rows (one float4 per thread)
            int r = t >> 5, k4 = (t & 31) << 2;
            int n = nb + r;
            float4 v = (n < NN) ? *(const float4*)(x + (size_t)n * 128 + k4)
                                : make_float4(0.f, 0.f, 0.f, 0.f);
            *(float4*)(sx + r * 128 + k4) = v;
        }
        __syncthreads();

        float acc[8];
#pragma unroll
        for (int r = 0; r < 8; r++) acc[r] = bias;
#pragma unroll 4
        for (int k4 = 0; k4 < 32; k4++) {
            float4 w = *(const float4*)(wrow + k4 * 4);
#pragma unroll
            for (int r = 0; r < 8; r++) {
                float4 xv = *(const float4*)(sx + r * 128 + k4 * 4);
                acc[r] += w.x * xv.x + w.y * xv.y + w.z * xv.z + w.w * xv.w;
            }
        }
#pragma unroll
        for (int r = 0; r < 8; r++) {
            int n = nb + r;
            if (n < NN) outbase[(size_t)n * 128 + j] = acc[r];
        }
        __syncthreads();
    }
}

// ---------------- layer-1 edge pass A: logits + segment max ----------------
// one warp per edge; lanes 0-15 = head 0 (ch 0..63), lanes 16-31 = head 1
__global__ void k_edge1_logit(const int* __restrict__ ei,
                              const float* __restrict__ att) {
    int w = (blockIdx.x * blockDim.x + threadIdx.x) >> 5;
    if (w >= ETOT) return;
    int lane = threadIdx.x & 31;
    int s, d;
    if (w < EE) { s = ei[w]; d = ei[EE + w]; }
    else        { s = d = w - EE; }

    float4 a = *(const float4*)(g_xl1 + (size_t)s * 128 + lane * 4);
    float4 b = *(const float4*)(g_xr1 + (size_t)d * 128 + lane * 4);
    float4 wa = *(const float4*)(att + lane * 4);
    float p = wa.x * lrelu(a.x + b.x, 0.2f) + wa.y * lrelu(a.y + b.y, 0.2f)
            + wa.z * lrelu(a.z + b.z, 0.2f) + wa.w * lrelu(a.w + b.w, 0.2f);
    p += __shfl_xor_sync(0xffffffffu, p, 8);
    p += __shfl_xor_sync(0xffffffffu, p, 4);
    p += __shfl_xor_sync(0xffffffffu, p, 2);
    p += __shfl_xor_sync(0xffffffffu, p, 1);
    if ((lane & 15) == 0) {
        int h = lane >> 4;
        g_lg1[(size_t)w * 2 + h] = p;
        atomicMaxF(&g_mx1[d * 2 + h], p);
    }
}

// ---------------- layer-1 edge pass B: exp + segment sum ----------------
__global__ void k_edge1_exp(const int* __restrict__ ei) {
    int idx = blockIdx.x * blockDim.x + threadIdx.x;
    if (idx >= ETOT * 2) return;
    int e = idx >> 1, h = idx & 1;
    int d = (e < EE) ? ei[EE + e] : (e - EE);
    float ex = __expf(g_lg1[idx] - g_mx1[d * 2 + h]);
    g_lg1[idx] = ex;
    atomicAdd(&g_dn1[d * 2 + h], ex);
}

// ---------------- layer-1 edge pass C: weighted aggregation ----------------
__global__ void k_edge1_agg(const int* __restrict__ ei) {
    int w = (blockIdx.x * blockDim.x + threadIdx.x) >> 5;
    if (w >= ETOT) return;
    int lane = threadIdx.x & 31;
    int s, d;
    if (w < EE) { s = ei[w]; d = ei[EE + w]; }
    else        { s = d = w - EE; }
    int h = lane >> 4;
    float alpha = g_lg1[(size_t)w * 2 + h] / g_dn1[d * 2 + h];
    float4 a = *(const float4*)(g_xl1 + (size_t)s * 128 + lane * 4);
    float* o = g_out1 + (size_t)d * 128 + lane * 4;
    atomicAdd(o + 0, a.x * alpha);
    atomicAdd(o + 1, a.y * alpha);
    atomicAdd(o + 2, a.z * alpha);
    atomicAdd(o + 3, a.w * alpha);
}

// ---------------- layer-1 epilogue: +bias, leaky(0.01) in place ----------------
__global__ void k_node1(const float* __restrict__ bias1) {
    int i = blockIdx.x * blockDim.x + threadIdx.x;
    if (i >= NN * 128) return;
    g_out1[i] = lrelu(g_out1[i] + bias1[i & 127], 0.01f);
}

// ---------------- layer-2 node transforms: xl2/xr2 = h1 @ w^T + b ----------------
__global__ void k_gemm2(const float* __restrict__ wl, const float* __restrict__ bl,
                        const float* __restrict__ wr, const float* __restrict__ br) {
    extern __shared__ float sm[];
    float* sw = sm;                // 2 * 64 * 132
    float* sx = sm + 2 * 64 * 132; // 8 * 128
    int t = threadIdx.x; // 128

    for (int idx = t; idx < 64 * 32; idx += 128) {
        int j = idx >> 5, k4 = (idx & 31) << 2;
        *(float4*)(sw + j * 132 + k4)            = *(const float4*)(wl + j * 128 + k4);
        *(float4*)(sw + 64 * 132 + j * 132 + k4) = *(const float4*)(wr + j * 128 + k4);
    }
    __syncthreads();

    int half = t >> 6;
    int j    = t & 63;
    const float* wrow = sw + half * 64 * 132 + j * 132;
    float bias = half ? br[j] : bl[j];
    float* outbase = half ? g_xr2 : g_xl2;
    int node0 = blockIdx.x * 128;

    for (int gr = 0; gr < 16; gr++) {
        int nb = node0 + gr * 8;
        for (int idx = t; idx < 256; idx += 128) {
            int r = idx >> 5, k4 = (idx & 31) << 2;
            int n = nb + r;
            float4 v = (n < NN) ? *(const float4*)(g_out1 + (size_t)n * 128 + k4)
                                : make_float4(0.f, 0.f, 0.f, 0.f);
            *(float4*)(sx + r * 128 + k4) = v;
        }
        __syncthreads();

        float acc[8];
#pragma unroll
        for (int r = 0; r < 8; r++) acc[r] = bias;
#pragma unroll 4
        for (int k4 = 0; k4 < 32; k4++) {
            float4 w = *(const float4*)(wrow + k4 * 4);
#pragma unroll
            for (int r = 0; r < 8; r++) {
                float4 xv = *(const float4*)(sx + r * 128 + k4 * 4);
                acc[r] += w.x * xv.x + w.y * xv.y + w.z * xv.z + w.w * xv.w;
            }
        }
#pragma unroll
        for (int r = 0; r < 8; r++) {
            int n = nb + r;
            if (n < NN) outbase[(size_t)n * 64 + j] = acc[r];
        }
        __syncthreads();
    }
}

// ---------------- layer-2 edge passes (heads=1, 64 ch; lane covers 2 ch) ----------------
__global__ void k_edge2_logit(const int* __restrict__ ei,
                              const float* __restrict__ att) {
    int w = (blockIdx.x * blockDim.x + threadIdx.x) >> 5;
    if (w >= ETOT) return;
    int lane = threadIdx.x & 31;
    int s, d;
    if (w < EE) { s = ei[w]; d = ei[EE + w]; }
    else        { s = d = w - EE; }
    float2 a = *(const float2*)(g_xl2 + (size_t)s * 64 + lane * 2);
    float2 b = *(const float2*)(g_xr2 + (size_t)d * 64 + lane * 2);
    float2 wa = *(const float2*)(att + lane * 2);
    float p = wa.x * lrelu(a.x + b.x, 0.2f) + wa.y * lrelu(a.y + b.y, 0.2f);
    p += __shfl_xor_sync(0xffffffffu, p, 16);
    p += __shfl_xor_sync(0xffffffffu, p, 8);
    p += __shfl_xor_sync(0xffffffffu, p, 4);
    p += __shfl_xor_sync(0xffffffffu, p, 2);
    p += __shfl_xor_sync(0xffffffffu, p, 1);
    if (lane == 0) {
        g_lg2[w] = p;
        atomicMaxF(&g_mx2[d], p);
    }
}

__global__ void k_edge2_exp(const int* __restrict__ ei) {
    int e = blockIdx.x * blockDim.x + threadIdx.x;
    if (e >= ETOT) return;
    int d = (e < EE) ? ei[EE + e] : (e - EE);
    float ex = __expf(g_lg2[e] - g_mx2[d]);
    g_lg2[e] = ex;
    atomicAdd(&g_dn2[d], ex);
}

__global__ void k_edge2_agg(const int* __restrict__ ei) {
    int w = (blockIdx.x * blockDim.x + threadIdx.x) >> 5;
    if (w >= ETOT) return;
    int lane = threadIdx.x & 31;
    int s, d;
    if (w < EE) { s = ei[w]; d = ei[EE + w]; }
    else        { s = d = w - EE; }
    float alpha = g_lg2[w] / g_dn2[d];
    float2 a = *(const float2*)(g_xl2 + (size_t)s * 64 + lane * 2);
    float* o = g_out2 + (size_t)d * 64 + lane * 2;
    atomicAdd(o + 0, a.x * alpha);
    atomicAdd(o + 1, a.y * alpha);
}

// ---------------- layer-2 epilogue + mean-pool accumulation ----------------
__global__ void k_node2_pool(const float* __restrict__ bias2,
                             const int* __restrict__ batch) {
    int i = blockIdx.x * blockDim.x + threadIdx.x;
    if (i >= NN * 64) return;
    int n = i >> 6, c = i & 63;
    float v = lrelu(g_out2[i] + bias2[c], 0.01f);
    int b = batch[n];
    atomicAdd(&g_pool[b * 64 + c], v);
    if (c == 0) atomicAdd(&g_cnt[b], 1.f);
}

// ---------------- MLP head: mean, fc1+leaky, fc2 ----------------
__global__ void k_head(const float* __restrict__ fc1_w, const float* __restrict__ fc1_b,
                       const float* __restrict__ fc2_w, const float* __restrict__ fc2_b,
                       float* __restrict__ out) {
    __shared__ float p[64], q[64];
    int g = blockIdx.x, t = threadIdx.x;
    float cnt = fmaxf(g_cnt[g], 1.f);
    if (t < 64) p[t] = g_pool[g * 64 + t] / cnt;
    __syncthreads();
    if (t < 64) {
        float acc = fc1_b[t];
#pragma unroll
        for (int k = 0; k < 64; k++) acc += p[k] * fc1_w[t * 64 + k];
        q[t] = lrelu(acc, 0.01f);
    }
    __syncthreads();
    for (int o = t; o < 768; o += blockDim.x) {
        float acc = fc2_b[o];
#pragma unroll
        for (int k = 0; k < 64; k++) acc += q[k] * fc2_w[o * 64 + k];
        out[g * 768 + o] = acc;
    }
}

// ---------------- launch ----------------
extern "C" void kernel_launch(void* const* d_in, const int* in_sizes, int n_in,
                              void* d_out, int out_size) {
    const float* x     = (const float*)d_in[0];
    const int*   ei    = (const int*)d_in[1];     // int32: JAX x64 is disabled
    const int*   batch = (const int*)d_in[2];     // int32
    const float* w1_l = (const float*)d_in[3];
    const float* b1_l = (const float*)d_in[4];
    const float* w1_r = (const float*)d_in[5];
    const float* b1_r = (const float*)d_in[6];
    const float* att1 = (const float*)d_in[7];
    const float* bias1 = (const float*)d_in[8];
    const float* w2_l = (const float*)d_in[9];
    const float* b2_l = (const float*)d_in[10];
    const float* w2_r = (const float*)d_in[11];
    const float* b2_r = (const float*)d_in[12];
    const float* att2 = (const float*)d_in[13];
    const float* bias2 = (const float*)d_in[14];
    const float* fc1_w = (const float*)d_in[15];
    const float* fc1_b = (const float*)d_in[16];
    const float* fc2_w = (const float*)d_in[17];
    const float* fc2_b = (const float*)d_in[18];
    float* out = (float*)d_out;

    const int smem1 = (2 * 128 * 132 + 8 * 128) * 4; // 139264 B
    const int smem2 = (2 * 64 * 132 + 8 * 128) * 4;  //  71680 B
    cudaFuncSetAttribute(k_gemm1, cudaFuncAttributeMaxDynamicSharedMemorySize, smem1);
    cudaFuncSetAttribute(k_gemm2, cudaFuncAttributeMaxDynamicSharedMemorySize, smem2);

    // init accumulators
    k_init<<<(NN * 128 + 255) / 256, 256>>>();

    // layer 1
    k_gemm1<<<(NN + 127) / 128, 256, smem1>>>(x, w1_l, b1_l, w1_r, b1_r);
    {
        int thr = 256;
        int warps_grid = (ETOT * 32 + thr - 1) / thr;
        k_edge1_logit<<<warps_grid, thr>>>(ei, att1);
        k_edge1_exp<<<(ETOT * 2 + 255) / 256, 256>>>(ei);
        k_edge1_agg<<<warps_grid, thr>>>(ei);
    }
    k_node1<<<(NN * 128 + 255) / 256, 256>>>(bias1);

    // layer 2
    k_gemm2<<<(NN + 127) / 128, 128, smem2>>>(w2_l, b2_l, w2_r, b2_r);
    {
        int thr = 256;
        int warps_grid = (ETOT * 32 + thr - 1) / thr;
        k_edge2_logit<<<warps_grid, thr>>>(ei, att2);
        k_edge2_exp<<<(ETOT + 255) / 256, 256>>>(ei);
        k_edge2_agg<<<warps_grid, thr>>>(ei);
    }
    k_node2_pool<<<(NN * 64 + 255) / 256, 256>>>(bias2, batch);

    // head
    k_head<<<GG, 256>>>(fc1_w, fc1_b, fc2_w, fc2_b, out);
}

// round 6
// speedup vs baseline: 1.6883x; 1.6883x over previous
#include <cuda_runtime.h>

#define NN   50000
#define EE   800000
#define ETOT 850000
#define GG   256

// ---------------- scratch (device globals; no allocation allowed) ----------------
__device__ float g_xl1[NN * 128];
__device__ float g_xr1[NN * 128];
__device__ float g_out1[NN * 128];

__device__ float g_xl2[NN * 64];
__device__ float g_xr2[NN * 64];

__device__ float g_pool[GG * 64];
__device__ float g_cnt[GG];

__device__ int g_deg[NN];
__device__ int g_row[NN + 1];
__device__ int g_cursor[NN];
__device__ int g_csrc[ETOT];

__device__ __forceinline__ float lrelu(float v, float s) { return v > 0.f ? v : v * s; }

// ---------------- init: zero histogram + pool ----------------
__global__ void k_init() {
    int i = blockIdx.x * blockDim.x + threadIdx.x;
    if (i < NN) g_deg[i] = 0;
    if (i < GG * 64) g_pool[i] = 0.f;
    if (i < GG) g_cnt[i] = 0.f;
}

// ---------------- CSR build: histogram ----------------
__global__ void k_deg(const int* __restrict__ ei) {
    int e = blockIdx.x * blockDim.x + threadIdx.x;
    if (e >= ETOT) return;
    int d = (e < EE) ? ei[EE + e] : (e - EE);
    atomicAdd(&g_deg[d], 1);
}

// ---------------- CSR build: single-block exclusive scan over 50k ----------------
__global__ void k_scan() {
    __shared__ int ssum[1024];
    int t = threadIdx.x;
    const int CH = (NN + 1023) / 1024; // 49
    int lo = t * CH, hi = min(lo + CH, NN);
    int s = 0;
    for (int i = lo; i < hi; i++) s += g_deg[i];
    ssum[t] = s;
    __syncthreads();
    for (int off = 1; off < 1024; off <<= 1) {
        int v = 0;
        if (t >= off) v = ssum[t - off];
        __syncthreads();
        if (t >= off) ssum[t] += v;
        __syncthreads();
    }
    int run = (t == 0) ? 0 : ssum[t - 1];
    for (int i = lo; i < hi; i++) {
        g_row[i] = run;
        g_cursor[i] = run;
        run += g_deg[i];
    }
    if (t == 0) g_row[NN] = ETOT;
}

// ---------------- CSR build: scatter src by dst ----------------
__global__ void k_scatter(const int* __restrict__ ei) {
    int e = blockIdx.x * blockDim.x + threadIdx.x;
    if (e >= ETOT) return;
    int s, d;
    if (e < EE) { s = ei[e]; d = ei[EE + e]; }
    else        { s = d = e - EE; }
    int pos = atomicAdd(&g_cursor[d], 1);
    g_csrc[pos] = s;
}

// ---------------- layer-1 node transforms: xl1/xr1 = x @ w^T + b ----------------
__global__ void k_gemm1(const float* __restrict__ x,
                        const float* __restrict__ wl, const float* __restrict__ bl,
                        const float* __restrict__ wr, const float* __restrict__ br) {
    extern __shared__ float sm[];
    float* sw = sm;                 // 2 * 128 * 132 floats
    float* sx = sm + 2 * 128 * 132; // 8 * 128 floats
    int t = threadIdx.x;

    for (int idx = t; idx < 128 * 32; idx += 256) {
        int j = idx >> 5, k4 = (idx & 31) << 2;
        *(float4*)(sw + j * 132 + k4)             = *(const float4*)(wl + j * 128 + k4);
        *(float4*)(sw + 128 * 132 + j * 132 + k4) = *(const float4*)(wr + j * 128 + k4);
    }
    __syncthreads();

    int half = t >> 7;
    int j    = t & 127;
    const float* wrow = sw + half * 128 * 132 + j * 132;
    float bias = half ? br[j] : bl[j];
    float* outbase = half ? g_xr1 : g_xl1;
    int node0 = blockIdx.x * 128;

    for (int gr = 0; gr < 16; gr++) {
        int nb = node0 + gr * 8;
        {
            int r = t >> 5, k4 = (t & 31) << 2;
            int n = nb + r;
            float4 v = (n < NN) ? *(const float4*)(x + (size_t)n * 128 + k4)
                                : make_float4(0.f, 0.f, 0.f, 0.f);
            *(float4*)(sx + r * 128 + k4) = v;
        }
        __syncthreads();

        float acc[8];
#pragma unroll
        for (int r = 0; r < 8; r++) acc[r] = bias;
#pragma unroll 4
        for (int k4 = 0; k4 < 32; k4++) {
            float4 w = *(const float4*)(wrow + k4 * 4);
#pragma unroll
            for (int r = 0; r < 8; r++) {
                float4 xv = *(const float4*)(sx + r * 128 + k4 * 4);
                acc[r] += w.x * xv.x + w.y * xv.y + w.z * xv.z + w.w * xv.w;
            }
        }
#pragma unroll
        for (int r = 0; r < 8; r++) {
            int n = nb + r;
            if (n < NN) outbase[(size_t)n * 128 + j] = acc[r];
        }
        __syncthreads();
    }
}

// ---------------- layer-1 fused attention: online softmax + aggregate ----------------
// warp per dst; lanes 0-15 head0 (ch 4/lane), lanes 16-31 head1
__global__ void k_attn1(const float* __restrict__ att, const float* __restrict__ bias1) {
    int d = (blockIdx.x * blockDim.x + threadIdx.x) >> 5;
    if (d >= NN) return;
    int lane = threadIdx.x & 31;

    float4 b  = *(const float4*)(g_xr1 + (size_t)d * 128 + lane * 4);
    float4 wa = *(const float4*)(att + lane * 4);

    int rs = g_row[d], re = g_row[d + 1];
    float m = __int_as_float(0xff800000); // -inf
    float dn = 0.f;
    float4 acc = make_float4(0.f, 0.f, 0.f, 0.f);

    int s = (rs < re) ? g_csrc[rs] : 0;
    for (int pos = rs; pos < re; pos++) {
        float4 a = *(const float4*)(g_xl1 + (size_t)s * 128 + lane * 4);
        if (pos + 1 < re) s = g_csrc[pos + 1];

        float p = wa.x * lrelu(a.x + b.x, 0.2f) + wa.y * lrelu(a.y + b.y, 0.2f)
                + wa.z * lrelu(a.z + b.z, 0.2f) + wa.w * lrelu(a.w + b.w, 0.2f);
        p += __shfl_xor_sync(0xffffffffu, p, 8, 16);
        p += __shfl_xor_sync(0xffffffffu, p, 4, 16);
        p += __shfl_xor_sync(0xffffffffu, p, 2, 16);
        p += __shfl_xor_sync(0xffffffffu, p, 1, 16);

        float mn = fmaxf(m, p);
        float sc = __expf(m - mn);   // first iter: exp(-inf)=0
        float w  = __expf(p - mn);
        dn = dn * sc + w;
        acc.x = acc.x * sc + a.x * w;
        acc.y = acc.y * sc + a.y * w;
        acc.z = acc.z * sc + a.z * w;
        acc.w = acc.w * sc + a.w * w;
        m = mn;
    }

    float inv = 1.f / dn;
    float4 bi = *(const float4*)(bias1 + lane * 4);
    float4 o;
    o.x = lrelu(acc.x * inv + bi.x, 0.01f);
    o.y = lrelu(acc.y * inv + bi.y, 0.01f);
    o.z = lrelu(acc.z * inv + bi.z, 0.01f);
    o.w = lrelu(acc.w * inv + bi.w, 0.01f);
    *(float4*)(g_out1 + (size_t)d * 128 + lane * 4) = o;
}

// ---------------- layer-2 node transforms ----------------
__global__ void k_gemm2(const float* __restrict__ wl, const float* __restrict__ bl,
                        const float* __restrict__ wr, const float* __restrict__ br) {
    extern __shared__ float sm[];
    float* sw = sm;                // 2 * 64 * 132
    float* sx = sm + 2 * 64 * 132; // 8 * 128
    int t = threadIdx.x; // 128

    for (int idx = t; idx < 64 * 32; idx += 128) {
        int j = idx >> 5, k4 = (idx & 31) << 2;
        *(float4*)(sw + j * 132 + k4)            = *(const float4*)(wl + j * 128 + k4);
        *(float4*)(sw + 64 * 132 + j * 132 + k4) = *(const float4*)(wr + j * 128 + k4);
    }
    __syncthreads();

    int half = t >> 6;
    int j    = t & 63;
    const float* wrow = sw + half * 64 * 132 + j * 132;
    float bias = half ? br[j] : bl[j];
    float* outbase = half ? g_xr2 : g_xl2;
    int node0 = blockIdx.x * 128;

    for (int gr = 0; gr < 16; gr++) {
        int nb = node0 + gr * 8;
        for (int idx = t; idx < 256; idx += 128) {
            int r = idx >> 5, k4 = (idx & 31) << 2;
            int n = nb + r;
            float4 v = (n < NN) ? *(const float4*)(g_out1 + (size_t)n * 128 + k4)
                                : make_float4(0.f, 0.f, 0.f, 0.f);
            *(float4*)(sx + r * 128 + k4) = v;
        }
        __syncthreads();

        float acc[8];
#pragma unroll
        for (int r = 0; r < 8; r++) acc[r] = bias;
#pragma unroll 4
        for (int k4 = 0; k4 < 32; k4++) {
            float4 w = *(const float4*)(wrow + k4 * 4);
#pragma unroll
            for (int r = 0; r < 8; r++) {
                float4 xv = *(const float4*)(sx + r * 128 + k4 * 4);
                acc[r] += w.x * xv.x + w.y * xv.y + w.z * xv.z + w.w * xv.w;
            }
        }
#pragma unroll
        for (int r = 0; r < 8; r++) {
            int n = nb + r;
            if (n < NN) outbase[(size_t)n * 64 + j] = acc[r];
        }
        __syncthreads();
    }
}

// ---------------- layer-2 fused attention + activation + mean-pool ----------------
// warp per dst; heads=1, 64 ch; lane covers 2 ch; full-warp reduce
__global__ void k_attn2(const float* __restrict__ att, const float* __restrict__ bias2,
                        const int* __restrict__ batch) {
    int d = (blockIdx.x * blockDim.x + threadIdx.x) >> 5;
    if (d >= NN) return;
    int lane = threadIdx.x & 31;

    float2 b  = *(const float2*)(g_xr2 + (size_t)d * 64 + lane * 2);
    float2 wa = *(const float2*)(att + lane * 2);

    int rs = g_row[d], re = g_row[d + 1];
    float m = __int_as_float(0xff800000);
    float dn = 0.f;
    float2 acc = make_float2(0.f, 0.f);

    int s = (rs < re) ? g_csrc[rs] : 0;
    for (int pos = rs; pos < re; pos++) {
        float2 a = *(const float2*)(g_xl2 + (size_t)s * 64 + lane * 2);
        if (pos + 1 < re) s = g_csrc[pos + 1];

        float p = wa.x * lrelu(a.x + b.x, 0.2f) + wa.y * lrelu(a.y + b.y, 0.2f);
        p += __shfl_xor_sync(0xffffffffu, p, 16);
        p += __shfl_xor_sync(0xffffffffu, p, 8);
        p += __shfl_xor_sync(0xffffffffu, p, 4);
        p += __shfl_xor_sync(0xffffffffu, p, 2);
        p += __shfl_xor_sync(0xffffffffu, p, 1);

        float mn = fmaxf(m, p);
        float sc = __expf(m - mn);
        float w  = __expf(p - mn);
        dn = dn * sc + w;
        acc.x = acc.x * sc + a.x * w;
        acc.y = acc.y * sc + a.y * w;
        m = mn;
    }

    float inv = 1.f / dn;
    float2 bi = *(const float2*)(bias2 + lane * 2);
    float v0 = lrelu(acc.x * inv + bi.x, 0.01f);
    float v1 = lrelu(acc.y * inv + bi.y, 0.01f);

    int g = batch[d];
    atomicAdd(&g_pool[g * 64 + lane * 2 + 0], v0);
    atomicAdd(&g_pool[g * 64 + lane * 2 + 1], v1);
    if (lane == 0) atomicAdd(&g_cnt[g], 1.f);
}

// ---------------- MLP head: mean, fc1+leaky, fc2 ----------------
__global__ void k_head(const float* __restrict__ fc1_w, const float* __restrict__ fc1_b,
                       const float* __restrict__ fc2_w, const float* __restrict__ fc2_b,
                       float* __restrict__ out) {
    __shared__ float p[64], q[64];
    int g = blockIdx.x, t = threadIdx.x;
    float cnt = fmaxf(g_cnt[g], 1.f);
    if (t < 64) p[t] = g_pool[g * 64 + t] / cnt;
    __syncthreads();
    if (t < 64) {
        float acc = fc1_b[t];
#pragma unroll
        for (int k = 0; k < 64; k++) acc += p[k] * fc1_w[t * 64 + k];
        q[t] = lrelu(acc, 0.01f);
    }
    __syncthreads();
    for (int o = t; o < 768; o += blockDim.x) {
        float acc = fc2_b[o];
#pragma unroll
        for (int k = 0; k < 64; k++) acc += q[k] * fc2_w[o * 64 + k];
        out[g * 768 + o] = acc;
    }
}

// ---------------- launch ----------------
extern "C" void kernel_launch(void* const* d_in, const int* in_sizes, int n_in,
                              void* d_out, int out_size) {
    const float* x     = (const float*)d_in[0];
    const int*   ei    = (const int*)d_in[1];
    const int*   batch = (const int*)d_in[2];
    const float* w1_l = (const float*)d_in[3];
    const float* b1_l = (const float*)d_in[4];
    const float* w1_r = (const float*)d_in[5];
    const float* b1_r = (const float*)d_in[6];
    const float* att1 = (const float*)d_in[7];
    const float* bias1 = (const float*)d_in[8];
    const float* w2_l = (const float*)d_in[9];
    const float* b2_l = (const float*)d_in[10];
    const float* w2_r = (const float*)d_in[11];
    const float* b2_r = (const float*)d_in[12];
    const float* att2 = (const float*)d_in[13];
    const float* bias2 = (const float*)d_in[14];
    const float* fc1_w = (const float*)d_in[15];
    const float* fc1_b = (const float*)d_in[16];
    const float* fc2_w = (const float*)d_in[17];
    const float* fc2_b = (const float*)d_in[18];
    float* out = (float*)d_out;

    const int smem1 = (2 * 128 * 132 + 8 * 128) * 4; // 139264 B
    const int smem2 = (2 * 64 * 132 + 8 * 128) * 4;  //  71680 B
    cudaFuncSetAttribute(k_gemm1, cudaFuncAttributeMaxDynamicSharedMemorySize, smem1);
    cudaFuncSetAttribute(k_gemm2, cudaFuncAttributeMaxDynamicSharedMemorySize, smem2);

    // CSR build (per-call; graph inputs could differ between calls)
    k_init<<<(NN + 255) / 256, 256>>>();
    k_deg<<<(ETOT + 255) / 256, 256>>>(ei);
    k_scan<<<1, 1024>>>();
    k_scatter<<<(ETOT + 255) / 256, 256>>>(ei);

    // layer 1
    k_gemm1<<<(NN + 127) / 128, 256, smem1>>>(x, w1_l, b1_l, w1_r, b1_r);
    k_attn1<<<(NN * 32 + 255) / 256, 256>>>(att1, bias1);

    // layer 2
    k_gemm2<<<(NN + 127) / 128, 128, smem2>>>(w2_l, b2_l, w2_r, b2_r);
    k_attn2<<<(NN * 32 + 255) / 256, 256>>>(att2, bias2, batch);

    // head
    k_head<<<GG, 256>>>(fc1_w, fc1_b, fc2_w, fc2_b, out);
}

// round 7
// speedup vs baseline: 1.9063x; 1.1291x over previous
#include <cuda_runtime.h>
#include <mma.h>
using namespace nvcuda;

#define NN   50000
#define EE   800000
#define ETOT 850000
#define GG   256

// ---------------- scratch (device globals; no allocation allowed) ----------------
__device__ float g_xl1[NN * 128];
__device__ float g_xr1[NN * 128];
__device__ float g_out1[NN * 128];

__device__ float g_xl2[NN * 64];
__device__ float g_xr2[NN * 64];

__device__ float g_pool[GG * 64];
__device__ float g_cnt[GG];

__device__ int g_deg[NN];
__device__ int g_row[NN + 1];
__device__ int g_cursor[NN];
__device__ int g_csrc[ETOT];

__device__ __forceinline__ float lrelu(float v, float s) { return v > 0.f ? v : v * s; }

// ---------------- init: zero histogram + pool ----------------
__global__ void k_init() {
    int i = blockIdx.x * blockDim.x + threadIdx.x;
    if (i < NN) g_deg[i] = 0;
    if (i < GG * 64) g_pool[i] = 0.f;
    if (i < GG) g_cnt[i] = 0.f;
}

// ---------------- CSR build: histogram ----------------
__global__ void k_deg(const int* __restrict__ ei) {
    int e = blockIdx.x * blockDim.x + threadIdx.x;
    if (e >= ETOT) return;
    int d = (e < EE) ? ei[EE + e] : (e - EE);
    atomicAdd(&g_deg[d], 1);
}

// ---------------- CSR build: single-block exclusive scan over 50k ----------------
__global__ void k_scan() {
    __shared__ int ssum[1024];
    int t = threadIdx.x;
    const int CH = (NN + 1023) / 1024; // 49
    int lo = t * CH, hi = min(lo + CH, NN);
    int s = 0;
    for (int i = lo; i < hi; i++) s += g_deg[i];
    ssum[t] = s;
    __syncthreads();
    for (int off = 1; off < 1024; off <<= 1) {
        int v = 0;
        if (t >= off) v = ssum[t - off];
        __syncthreads();
        if (t >= off) ssum[t] += v;
        __syncthreads();
    }
    int run = (t == 0) ? 0 : ssum[t - 1];
    for (int i = lo; i < hi; i++) {
        g_row[i] = run;
        g_cursor[i] = run;
        run += g_deg[i];
    }
    if (t == 0) g_row[NN] = ETOT;
}

// ---------------- CSR build: scatter src by dst ----------------
__global__ void k_scatter(const int* __restrict__ ei) {
    int e = blockIdx.x * blockDim.x + threadIdx.x;
    if (e >= ETOT) return;
    int s, d;
    if (e < EE) { s = ei[e]; d = ei[EE + e]; }
    else        { s = d = e - EE; }
    int pos = atomicAdd(&g_cursor[d], 1);
    g_csrc[pos] = s;
}

// ---------------- layer-1 node transforms via tf32 wmma ----------------
// block: 32 nodes x 256 outputs; 8 warps = 2 node-subtiles x 4 out-subtiles(64ch)
__global__ void k_gemm1(const float* __restrict__ x,
                        const float* __restrict__ wl, const float* __restrict__ bl,
                        const float* __restrict__ wr, const float* __restrict__ br) {
    __shared__ float sa[32 * 136];
    __shared__ float st[8 * 256];
    int tid = threadIdx.x;
    int wid = tid >> 5, lane = tid & 31;
    int node0 = blockIdx.x * 32;

    // stage A tile (32 x 128), zero-padded past NN
    for (int i = tid; i < 1024; i += 256) {
        int f = i * 4;
        int r = f >> 7, c = f & 127;
        int n = node0 + r;
        float4 v = (n < NN) ? *(const float4*)(x + (size_t)n * 128 + c)
                            : make_float4(0.f, 0.f, 0.f, 0.f);
        *(float4*)(sa + r * 136 + c) = v;
    }
    __syncthreads();

    int wm = wid >> 2;   // node subtile
    int wn = wid & 3;    // out subtile (64 ch)
    const float* wbase = (wn < 2) ? wl : wr;
    int ncol0 = (wn & 1) * 64;

    wmma::fragment<wmma::accumulator, 16, 16, 8, float> acc[4];
#pragma unroll
    for (int i = 0; i < 4; i++) wmma::fill_fragment(acc[i], 0.f);

#pragma unroll
    for (int k = 0; k < 128; k += 8) {
        wmma::fragment<wmma::matrix_a, 16, 16, 8, wmma::precision::tf32, wmma::row_major> af;
        wmma::load_matrix_sync(af, sa + wm * 16 * 136 + k, 136);
#pragma unroll
        for (int i = 0; i < af.num_elements; i++) af.x[i] = wmma::__float_to_tf32(af.x[i]);
#pragma unroll
        for (int fi = 0; fi < 4; fi++) {
            wmma::fragment<wmma::matrix_b, 16, 16, 8, wmma::precision::tf32, wmma::col_major> bf;
            wmma::load_matrix_sync(bf, wbase + (size_t)(ncol0 + fi * 16) * 128 + k, 128);
#pragma unroll
            for (int i = 0; i < bf.num_elements; i++) bf.x[i] = wmma::__float_to_tf32(bf.x[i]);
            wmma::mma_sync(acc[fi], af, bf, acc[fi]);
        }
    }

    // epilogue: stage each 16x16 frag, add bias, route to xl1/xr1
    float* stw = st + wid * 256;
#pragma unroll
    for (int fi = 0; fi < 4; fi++) {
        wmma::store_matrix_sync(stw, acc[fi], 16, wmma::mem_row_major);
        __syncwarp();
        int ch = wn * 64 + fi * 16;
        const float* bias = (ch < 128) ? bl : br;
        float* outb = (ch < 128) ? g_xl1 : g_xr1;
        int chl = ch & 127;
        for (int e = lane; e < 256; e += 32) {
            int r = e >> 4, c = e & 15;
            int n = node0 + wm * 16 + r;
            if (n < NN) outb[(size_t)n * 128 + chl + c] = stw[e] + bias[chl + c];
        }
        __syncwarp();
    }
}

// ---------------- layer-1 fused attention: online softmax + aggregate ----------------
__global__ void k_attn1(const float* __restrict__ att, const float* __restrict__ bias1) {
    int d = (blockIdx.x * blockDim.x + threadIdx.x) >> 5;
    if (d >= NN) return;
    int lane = threadIdx.x & 31;

    float4 b  = *(const float4*)(g_xr1 + (size_t)d * 128 + lane * 4);
    float4 wa = *(const float4*)(att + lane * 4);

    int rs = g_row[d], re = g_row[d + 1];
    float m = __int_as_float(0xff800000);
    float dn = 0.f;
    float4 acc = make_float4(0.f, 0.f, 0.f, 0.f);

    int s = (rs < re) ? g_csrc[rs] : 0;
    for (int pos = rs; pos < re; pos++) {
        float4 a = *(const float4*)(g_xl1 + (size_t)s * 128 + lane * 4);
        if (pos + 1 < re) s = g_csrc[pos + 1];

        float p = wa.x * lrelu(a.x + b.x, 0.2f) + wa.y * lrelu(a.y + b.y, 0.2f)
                + wa.z * lrelu(a.z + b.z, 0.2f) + wa.w * lrelu(a.w + b.w, 0.2f);
        p += __shfl_xor_sync(0xffffffffu, p, 8, 16);
        p += __shfl_xor_sync(0xffffffffu, p, 4, 16);
        p += __shfl_xor_sync(0xffffffffu, p, 2, 16);
        p += __shfl_xor_sync(0xffffffffu, p, 1, 16);

        float mn = fmaxf(m, p);
        float sc = __expf(m - mn);
        float w  = __expf(p - mn);
        dn = dn * sc + w;
        acc.x = acc.x * sc + a.x * w;
        acc.y = acc.y * sc + a.y * w;
        acc.z = acc.z * sc + a.z * w;
        acc.w = acc.w * sc + a.w * w;
        m = mn;
    }

    float inv = 1.f / dn;
    float4 bi = *(const float4*)(bias1 + lane * 4);
    float4 o;
    o.x = lrelu(acc.x * inv + bi.x, 0.01f);
    o.y = lrelu(acc.y * inv + bi.y, 0.01f);
    o.z = lrelu(acc.z * inv + bi.z, 0.01f);
    o.w = lrelu(acc.w * inv + bi.w, 0.01f);
    *(float4*)(g_out1 + (size_t)d * 128 + lane * 4) = o;
}

// ---------------- layer-2 node transforms via tf32 wmma ----------------
// block: 32 nodes x 128 outputs; 8 warps = 2 node-subtiles x 4 out-subtiles(32ch)
__global__ void k_gemm2(const float* __restrict__ wl, const float* __restrict__ bl,
                        const float* __restrict__ wr, const float* __restrict__ br) {
    __shared__ float sa[32 * 136];
    __shared__ float st[8 * 256];
    int tid = threadIdx.x;
    int wid = tid >> 5, lane = tid & 31;
    int node0 = blockIdx.x * 32;

    for (int i = tid; i < 1024; i += 256) {
        int f = i * 4;
        int r = f >> 7, c = f & 127;
        int n = node0 + r;
        float4 v = (n < NN) ? *(const float4*)(g_out1 + (size_t)n * 128 + c)
                            : make_float4(0.f, 0.f, 0.f, 0.f);
        *(float4*)(sa + r * 136 + c) = v;
    }
    __syncthreads();

    int wm = wid >> 2;
    int wn = wid & 3;    // 32 ch each
    const float* wbase = (wn < 2) ? wl : wr;
    int ncol0 = (wn & 1) * 32;

    wmma::fragment<wmma::accumulator, 16, 16, 8, float> acc[2];
#pragma unroll
    for (int i = 0; i < 2; i++) wmma::fill_fragment(acc[i], 0.f);

#pragma unroll
    for (int k = 0; k < 128; k += 8) {
        wmma::fragment<wmma::matrix_a, 16, 16, 8, wmma::precision::tf32, wmma::row_major> af;
        wmma::load_matrix_sync(af, sa + wm * 16 * 136 + k, 136);
#pragma unroll
        for (int i = 0; i < af.num_elements; i++) af.x[i] = wmma::__float_to_tf32(af.x[i]);
#pragma unroll
        for (int fi = 0; fi < 2; fi++) {
            wmma::fragment<wmma::matrix_b, 16, 16, 8, wmma::precision::tf32, wmma::col_major> bf;
            wmma::load_matrix_sync(bf, wbase + (size_t)(ncol0 + fi * 16) * 128 + k, 128);
#pragma unroll
            for (int i = 0; i < bf.num_elements; i++) bf.x[i] = wmma::__float_to_tf32(bf.x[i]);
            wmma::mma_sync(acc[fi], af, bf, acc[fi]);
        }
    }

    float* stw = st + wid * 256;
#pragma unroll
    for (int fi = 0; fi < 2; fi++) {
        wmma::store_matrix_sync(stw, acc[fi], 16, wmma::mem_row_major);
        __syncwarp();
        int ch = wn * 32 + fi * 16;       // 0..127
        const float* bias = (ch < 64) ? bl : br;
        float* outb = (ch < 64) ? g_xl2 : g_xr2;
        int chl = ch & 63;
        for (int e = lane; e < 256; e += 32) {
            int r = e >> 4, c = e & 15;
            int n = node0 + wm * 16 + r;
            if (n < NN) outb[(size_t)n * 64 + chl + c] = stw[e] + bias[chl + c];
        }
        __syncwarp();
    }
}

// ---------------- layer-2 fused attention + activation + mean-pool ----------------
__global__ void k_attn2(const float* __restrict__ att, const float* __restrict__ bias2,
                        const int* __restrict__ batch) {
    int d = (blockIdx.x * blockDim.x + threadIdx.x) >> 5;
    if (d >= NN) return;
    int lane = threadIdx.x & 31;

    float2 b  = *(const float2*)(g_xr2 + (size_t)d * 64 + lane * 2);
    float2 wa = *(const float2*)(att + lane * 2);

    int rs = g_row[d], re = g_row[d + 1];
    float m = __int_as_float(0xff800000);
    float dn = 0.f;
    float2 acc = make_float2(0.f, 0.f);

    int s = (rs < re) ? g_csrc[rs] : 0;
    for (int pos = rs; pos < re; pos++) {
        float2 a = *(const float2*)(g_xl2 + (size_t)s * 64 + lane * 2);
        if (pos + 1 < re) s = g_csrc[pos + 1];

        float p = wa.x * lrelu(a.x + b.x, 0.2f) + wa.y * lrelu(a.y + b.y, 0.2f);
        p += __shfl_xor_sync(0xffffffffu, p, 16);
        p += __shfl_xor_sync(0xffffffffu, p, 8);
        p += __shfl_xor_sync(0xffffffffu, p, 4);
        p += __shfl_xor_sync(0xffffffffu, p, 2);
        p += __shfl_xor_sync(0xffffffffu, p, 1);

        float mn = fmaxf(m, p);
        float sc = __expf(m - mn);
        float w  = __expf(p - mn);
        dn = dn * sc + w;
        acc.x = acc.x * sc + a.x * w;
        acc.y = acc.y * sc + a.y * w;
        m = mn;
    }

    float inv = 1.f / dn;
    float2 bi = *(const float2*)(bias2 + lane * 2);
    float v0 = lrelu(acc.x * inv + bi.x, 0.01f);
    float v1 = lrelu(acc.y * inv + bi.y, 0.01f);

    int g = batch[d];
    atomicAdd(&g_pool[g * 64 + lane * 2 + 0], v0);
    atomicAdd(&g_pool[g * 64 + lane * 2 + 1], v1);
    if (lane == 0) atomicAdd(&g_cnt[g], 1.f);
}

// ---------------- MLP head: mean, fc1+leaky, fc2 ----------------
__global__ void k_head(const float* __restrict__ fc1_w, const float* __restrict__ fc1_b,
                       const float* __restrict__ fc2_w, const float* __restrict__ fc2_b,
                       float* __restrict__ out) {
    __shared__ float p[64], q[64];
    int g = blockIdx.x, t = threadIdx.x;
    float cnt = fmaxf(g_cnt[g], 1.f);
    if (t < 64) p[t] = g_pool[g * 64 + t] / cnt;
    __syncthreads();
    if (t < 64) {
        float acc = fc1_b[t];
#pragma unroll
        for (int k = 0; k < 64; k++) acc += p[k] * fc1_w[t * 64 + k];
        q[t] = lrelu(acc, 0.01f);
    }
    __syncthreads();
    for (int o = t; o < 768; o += blockDim.x) {
        float acc = fc2_b[o];
#pragma unroll
        for (int k = 0; k < 64; k++) acc += q[k] * fc2_w[o * 64 + k];
        out[g * 768 + o] = acc;
    }
}

// ---------------- launch ----------------
extern "C" void kernel_launch(void* const* d_in, const int* in_sizes, int n_in,
                              void* d_out, int out_size) {
    const float* x     = (const float*)d_in[0];
    const int*   ei    = (const int*)d_in[1];
    const int*   batch = (const int*)d_in[2];
    const float* w1_l = (const float*)d_in[3];
    const float* b1_l = (const float*)d_in[4];
    const float* w1_r = (const float*)d_in[5];
    const float* b1_r = (const float*)d_in[6];
    const float* att1 = (const float*)d_in[7];
    const float* bias1 = (const float*)d_in[8];
    const float* w2_l = (const float*)d_in[9];
    const float* b2_l = (const float*)d_in[10];
    const float* w2_r = (const float*)d_in[11];
    const float* b2_r = (const float*)d_in[12];
    const float* att2 = (const float*)d_in[13];
    const float* bias2 = (const float*)d_in[14];
    const float* fc1_w = (const float*)d_in[15];
    const float* fc1_b = (const float*)d_in[16];
    const float* fc2_w = (const float*)d_in[17];
    const float* fc2_b = (const float*)d_in[18];
    float* out = (float*)d_out;

    // CSR build
    k_init<<<(NN + 255) / 256, 256>>>();
    k_deg<<<(ETOT + 255) / 256, 256>>>(ei);
    k_scan<<<1, 1024>>>();
    k_scatter<<<(ETOT + 255) / 256, 256>>>(ei);

    // layer 1
    k_gemm1<<<(NN + 31) / 32, 256>>>(x, w1_l, b1_l, w1_r, b1_r);
    k_attn1<<<(NN * 32 + 255) / 256, 256>>>(att1, bias1);

    // layer 2
    k_gemm2<<<(NN + 31) / 32, 256>>>(w2_l, b2_l, w2_r, b2_r);
    k_attn2<<<(NN * 32 + 255) / 256, 256>>>(att2, bias2, batch);

    // head
    k_head<<<GG, 256>>>(fc1_w, fc1_b, fc2_w, fc2_b, out);
}

// round 8
// speedup vs baseline: 1.9592x; 1.0277x over previous
#include <cuda_runtime.h>
#include <mma.h>
using namespace nvcuda;

#define NN   50000
#define EE   800000
#define ETOT 850000
#define GG   256

// ---------------- scratch (device globals; no allocation allowed) ----------------
__device__ float g_xl1[NN * 128];
__device__ float g_xr1[NN * 128];
__device__ float g_out1[NN * 128];

__device__ float g_xl2[NN * 64];
__device__ float g_xr2[NN * 64];

__device__ float g_pool[GG * 64];
__device__ float g_cnt[GG];

__device__ int g_deg[NN];
__device__ int g_row[NN + 1];
__device__ int g_cursor[NN];
__device__ int g_csrc[ETOT];

__device__ __forceinline__ float lrelu(float v, float s) { return v > 0.f ? v : v * s; }

// ---------------- init: zero histogram + pool ----------------
__global__ void k_init() {
    int i = blockIdx.x * blockDim.x + threadIdx.x;
    if (i < NN) g_deg[i] = 0;
    if (i < GG * 64) g_pool[i] = 0.f;
    if (i < GG) g_cnt[i] = 0.f;
}

// ---------------- CSR build: histogram ----------------
__global__ void k_deg(const int* __restrict__ ei) {
    int e = blockIdx.x * blockDim.x + threadIdx.x;
    if (e >= ETOT) return;
    int d = (e < EE) ? ei[EE + e] : (e - EE);
    atomicAdd(&g_deg[d], 1);
}

// ---------------- CSR build: single-block exclusive scan over 50k ----------------
__global__ void k_scan() {
    __shared__ int ssum[1024];
    int t = threadIdx.x;
    const int CH = (NN + 1023) / 1024; // 49
    int lo = t * CH, hi = min(lo + CH, NN);
    int s = 0;
    for (int i = lo; i < hi; i++) s += g_deg[i];
    ssum[t] = s;
    __syncthreads();
    for (int off = 1; off < 1024; off <<= 1) {
        int v = 0;
        if (t >= off) v = ssum[t - off];
        __syncthreads();
        if (t >= off) ssum[t] += v;
        __syncthreads();
    }
    int run = (t == 0) ? 0 : ssum[t - 1];
    for (int i = lo; i < hi; i++) {
        g_row[i] = run;
        g_cursor[i] = run;
        run += g_deg[i];
    }
    if (t == 0) g_row[NN] = ETOT;
}

// ---------------- CSR build: scatter src by dst ----------------
__global__ void k_scatter(const int* __restrict__ ei) {
    int e = blockIdx.x * blockDim.x + threadIdx.x;
    if (e >= ETOT) return;
    int s, d;
    if (e < EE) { s = ei[e]; d = ei[EE + e]; }
    else        { s = d = e - EE; }
    int pos = atomicAdd(&g_cursor[d], 1);
    g_csrc[pos] = s;
}

// ---------------- layer-1 node transforms via tf32 wmma ----------------
__global__ void k_gemm1(const float* __restrict__ x,
                        const float* __restrict__ wl, const float* __restrict__ bl,
                        const float* __restrict__ wr, const float* __restrict__ br) {
    __shared__ float sa[32 * 136];
    __shared__ float st[8 * 256];
    int tid = threadIdx.x;
    int wid = tid >> 5, lane = tid & 31;
    int node0 = blockIdx.x * 32;

    for (int i = tid; i < 1024; i += 256) {
        int f = i * 4;
        int r = f >> 7, c = f & 127;
        int n = node0 + r;
        float4 v = (n < NN) ? *(const float4*)(x + (size_t)n * 128 + c)
                            : make_float4(0.f, 0.f, 0.f, 0.f);
        *(float4*)(sa + r * 136 + c) = v;
    }
    __syncthreads();

    int wm = wid >> 2;
    int wn = wid & 3;
    const float* wbase = (wn < 2) ? wl : wr;
    int ncol0 = (wn & 1) * 64;

    wmma::fragment<wmma::accumulator, 16, 16, 8, float> acc[4];
#pragma unroll
    for (int i = 0; i < 4; i++) wmma::fill_fragment(acc[i], 0.f);

#pragma unroll
    for (int k = 0; k < 128; k += 8) {
        wmma::fragment<wmma::matrix_a, 16, 16, 8, wmma::precision::tf32, wmma::row_major> af;
        wmma::load_matrix_sync(af, sa + wm * 16 * 136 + k, 136);
#pragma unroll
        for (int i = 0; i < af.num_elements; i++) af.x[i] = wmma::__float_to_tf32(af.x[i]);
#pragma unroll
        for (int fi = 0; fi < 4; fi++) {
            wmma::fragment<wmma::matrix_b, 16, 16, 8, wmma::precision::tf32, wmma::col_major> bf;
            wmma::load_matrix_sync(bf, wbase + (size_t)(ncol0 + fi * 16) * 128 + k, 128);
#pragma unroll
            for (int i = 0; i < bf.num_elements; i++) bf.x[i] = wmma::__float_to_tf32(bf.x[i]);
            wmma::mma_sync(acc[fi], af, bf, acc[fi]);
        }
    }

    float* stw = st + wid * 256;
#pragma unroll
    for (int fi = 0; fi < 4; fi++) {
        wmma::store_matrix_sync(stw, acc[fi], 16, wmma::mem_row_major);
        __syncwarp();
        int ch = wn * 64 + fi * 16;
        const float* bias = (ch < 128) ? bl : br;
        float* outb = (ch < 128) ? g_xl1 : g_xr1;
        int chl = ch & 127;
        for (int e = lane; e < 256; e += 32) {
            int r = e >> 4, c = e & 15;
            int n = node0 + wm * 16 + r;
            if (n < NN) outb[(size_t)n * 128 + chl + c] = stw[e] + bias[chl + c];
        }
        __syncwarp();
    }
}

// ---------------- layer-1 fused attention: 4x-unrolled online softmax ----------------
// warp per dst; lanes 0-15 head0 (4 ch/lane), lanes 16-31 head1
__global__ void k_attn1(const float* __restrict__ att, const float* __restrict__ bias1) {
    int d = (blockIdx.x * blockDim.x + threadIdx.x) >> 5;
    if (d >= NN) return;
    int lane = threadIdx.x & 31;

    float4 b  = *(const float4*)(g_xr1 + (size_t)d * 128 + lane * 4);
    float4 wa = *(const float4*)(att + lane * 4);

    int rs = g_row[d], re = g_row[d + 1];
    float m = __int_as_float(0xff800000);
    float dn = 0.f;
    float4 acc = make_float4(0.f, 0.f, 0.f, 0.f);

    int pos = rs;
    // ---- 4-edge batches: gathers + reductions overlapped ----
    for (; pos + 4 <= re; pos += 4) {
        int s0 = g_csrc[pos], s1 = g_csrc[pos + 1], s2 = g_csrc[pos + 2], s3 = g_csrc[pos + 3];
        float4 a0 = *(const float4*)(g_xl1 + (size_t)s0 * 128 + lane * 4);
        float4 a1 = *(const float4*)(g_xl1 + (size_t)s1 * 128 + lane * 4);
        float4 a2 = *(const float4*)(g_xl1 + (size_t)s2 * 128 + lane * 4);
        float4 a3 = *(const float4*)(g_xl1 + (size_t)s3 * 128 + lane * 4);

        float p0 = wa.x * lrelu(a0.x + b.x, 0.2f) + wa.y * lrelu(a0.y + b.y, 0.2f)
                 + wa.z * lrelu(a0.z + b.z, 0.2f) + wa.w * lrelu(a0.w + b.w, 0.2f);
        float p1 = wa.x * lrelu(a1.x + b.x, 0.2f) + wa.y * lrelu(a1.y + b.y, 0.2f)
                 + wa.z * lrelu(a1.z + b.z, 0.2f) + wa.w * lrelu(a1.w + b.w, 0.2f);
        float p2 = wa.x * lrelu(a2.x + b.x, 0.2f) + wa.y * lrelu(a2.y + b.y, 0.2f)
                 + wa.z * lrelu(a2.z + b.z, 0.2f) + wa.w * lrelu(a2.w + b.w, 0.2f);
        float p3 = wa.x * lrelu(a3.x + b.x, 0.2f) + wa.y * lrelu(a3.y + b.y, 0.2f)
                 + wa.z * lrelu(a3.z + b.z, 0.2f) + wa.w * lrelu(a3.w + b.w, 0.2f);

#pragma unroll
        for (int sh = 8; sh >= 1; sh >>= 1) {
            p0 += __shfl_xor_sync(0xffffffffu, p0, sh, 16);
            p1 += __shfl_xor_sync(0xffffffffu, p1, sh, 16);
            p2 += __shfl_xor_sync(0xffffffffu, p2, sh, 16);
            p3 += __shfl_xor_sync(0xffffffffu, p3, sh, 16);
        }

        float mn = fmaxf(fmaxf(m, p0), fmaxf(fmaxf(p1, p2), p3));
        float sc = __expf(m - mn);
        float w0 = __expf(p0 - mn), w1 = __expf(p1 - mn);
        float w2 = __expf(p2 - mn), w3 = __expf(p3 - mn);
        dn = dn * sc + (w0 + w1) + (w2 + w3);
        acc.x = acc.x * sc + a0.x * w0 + a1.x * w1 + a2.x * w2 + a3.x * w3;
        acc.y = acc.y * sc + a0.y * w0 + a1.y * w1 + a2.y * w2 + a3.y * w3;
        acc.z = acc.z * sc + a0.z * w0 + a1.z * w1 + a2.z * w2 + a3.z * w3;
        acc.w = acc.w * sc + a0.w * w0 + a1.w * w1 + a2.w * w2 + a3.w * w3;
        m = mn;
    }
    // ---- tail ----
    for (; pos < re; pos++) {
        int s = g_csrc[pos];
        float4 a = *(const float4*)(g_xl1 + (size_t)s * 128 + lane * 4);
        float p = wa.x * lrelu(a.x + b.x, 0.2f) + wa.y * lrelu(a.y + b.y, 0.2f)
                + wa.z * lrelu(a.z + b.z, 0.2f) + wa.w * lrelu(a.w + b.w, 0.2f);
#pragma unroll
        for (int sh = 8; sh >= 1; sh >>= 1)
            p += __shfl_xor_sync(0xffffffffu, p, sh, 16);
        float mn = fmaxf(m, p);
        float sc = __expf(m - mn);
        float w  = __expf(p - mn);
        dn = dn * sc + w;
        acc.x = acc.x * sc + a.x * w;
        acc.y = acc.y * sc + a.y * w;
        acc.z = acc.z * sc + a.z * w;
        acc.w = acc.w * sc + a.w * w;
        m = mn;
    }

    float inv = 1.f / dn;
    float4 bi = *(const float4*)(bias1 + lane * 4);
    float4 o;
    o.x = lrelu(acc.x * inv + bi.x, 0.01f);
    o.y = lrelu(acc.y * inv + bi.y, 0.01f);
    o.z = lrelu(acc.z * inv + bi.z, 0.01f);
    o.w = lrelu(acc.w * inv + bi.w, 0.01f);
    *(float4*)(g_out1 + (size_t)d * 128 + lane * 4) = o;
}

// ---------------- layer-2 node transforms via tf32 wmma ----------------
__global__ void k_gemm2(const float* __restrict__ wl, const float* __restrict__ bl,
                        const float* __restrict__ wr, const float* __restrict__ br) {
    __shared__ float sa[32 * 136];
    __shared__ float st[8 * 256];
    int tid = threadIdx.x;
    int wid = tid >> 5, lane = tid & 31;
    int node0 = blockIdx.x * 32;

    for (int i = tid; i < 1024; i += 256) {
        int f = i * 4;
        int r = f >> 7, c = f & 127;
        int n = node0 + r;
        float4 v = (n < NN) ? *(const float4*)(g_out1 + (size_t)n * 128 + c)
                            : make_float4(0.f, 0.f, 0.f, 0.f);
        *(float4*)(sa + r * 136 + c) = v;
    }
    __syncthreads();

    int wm = wid >> 2;
    int wn = wid & 3;
    const float* wbase = (wn < 2) ? wl : wr;
    int ncol0 = (wn & 1) * 32;

    wmma::fragment<wmma::accumulator, 16, 16, 8, float> acc[2];
#pragma unroll
    for (int i = 0; i < 2; i++) wmma::fill_fragment(acc[i], 0.f);

#pragma unroll
    for (int k = 0; k < 128; k += 8) {
        wmma::fragment<wmma::matrix_a, 16, 16, 8, wmma::precision::tf32, wmma::row_major> af;
        wmma::load_matrix_sync(af, sa + wm * 16 * 136 + k, 136);
#pragma unroll
        for (int i = 0; i < af.num_elements; i++) af.x[i] = wmma::__float_to_tf32(af.x[i]);
#pragma unroll
        for (int fi = 0; fi < 2; fi++) {
            wmma::fragment<wmma::matrix_b, 16, 16, 8, wmma::precision::tf32, wmma::col_major> bf;
            wmma::load_matrix_sync(bf, wbase + (size_t)(ncol0 + fi * 16) * 128 + k, 128);
#pragma unroll
            for (int i = 0; i < bf.num_elements; i++) bf.x[i] = wmma::__float_to_tf32(bf.x[i]);
            wmma::mma_sync(acc[fi], af, bf, acc[fi]);
        }
    }

    float* stw = st + wid * 256;
#pragma unroll
    for (int fi = 0; fi < 2; fi++) {
        wmma::store_matrix_sync(stw, acc[fi], 16, wmma::mem_row_major);
        __syncwarp();
        int ch = wn * 32 + fi * 16;
        const float* bias = (ch < 64) ? bl : br;
        float* outb = (ch < 64) ? g_xl2 : g_xr2;
        int chl = ch & 63;
        for (int e = lane; e < 256; e += 32) {
            int r = e >> 4, c = e & 15;
            int n = node0 + wm * 16 + r;
            if (n < NN) outb[(size_t)n * 64 + chl + c] = stw[e] + bias[chl + c];
        }
        __syncwarp();
    }
}

// ---------------- layer-2 fused attention: 4x-unrolled + mean-pool ----------------
__global__ void k_attn2(const float* __restrict__ att, const float* __restrict__ bias2,
                        const int* __restrict__ batch) {
    int d = (blockIdx.x * blockDim.x + threadIdx.x) >> 5;
    if (d >= NN) return;
    int lane = threadIdx.x & 31;

    float2 b  = *(const float2*)(g_xr2 + (size_t)d * 64 + lane * 2);
    float2 wa = *(const float2*)(att + lane * 2);

    int rs = g_row[d], re = g_row[d + 1];
    float m = __int_as_float(0xff800000);
    float dn = 0.f;
    float2 acc = make_float2(0.f, 0.f);

    int pos = rs;
    for (; pos + 4 <= re; pos += 4) {
        int s0 = g_csrc[pos], s1 = g_csrc[pos + 1], s2 = g_csrc[pos + 2], s3 = g_csrc[pos + 3];
        float2 a0 = *(const float2*)(g_xl2 + (size_t)s0 * 64 + lane * 2);
        float2 a1 = *(const float2*)(g_xl2 + (size_t)s1 * 64 + lane * 2);
        float2 a2 = *(const float2*)(g_xl2 + (size_t)s2 * 64 + lane * 2);
        float2 a3 = *(const float2*)(g_xl2 + (size_t)s3 * 64 + lane * 2);

        float p0 = wa.x * lrelu(a0.x + b.x, 0.2f) + wa.y * lrelu(a0.y + b.y, 0.2f);
        float p1 = wa.x * lrelu(a1.x + b.x, 0.2f) + wa.y * lrelu(a1.y + b.y, 0.2f);
        float p2 = wa.x * lrelu(a2.x + b.x, 0.2f) + wa.y * lrelu(a2.y + b.y, 0.2f);
        float p3 = wa.x * lrelu(a3.x + b.x, 0.2f) + wa.y * lrelu(a3.y + b.y, 0.2f);

#pragma unroll
        for (int sh = 16; sh >= 1; sh >>= 1) {
            p0 += __shfl_xor_sync(0xffffffffu, p0, sh);
            p1 += __shfl_xor_sync(0xffffffffu, p1, sh);
            p2 += __shfl_xor_sync(0xffffffffu, p2, sh);
            p3 += __shfl_xor_sync(0xffffffffu, p3, sh);
        }

        float mn = fmaxf(fmaxf(m, p0), fmaxf(fmaxf(p1, p2), p3));
        float sc = __expf(m - mn);
        float w0 = __expf(p0 - mn), w1 = __expf(p1 - mn);
        float w2 = __expf(p2 - mn), w3 = __expf(p3 - mn);
        dn = dn * sc + (w0 + w1) + (w2 + w3);
        acc.x = acc.x * sc + a0.x * w0 + a1.x * w1 + a2.x * w2 + a3.x * w3;
        acc.y = acc.y * sc + a0.y * w0 + a1.y * w1 + a2.y * w2 + a3.y * w3;
        m = mn;
    }
    for (; pos < re; pos++) {
        int s = g_csrc[pos];
        float2 a = *(const float2*)(g_xl2 + (size_t)s * 64 + lane * 2);
        float p = wa.x * lrelu(a.x + b.x, 0.2f) + wa.y * lrelu(a.y + b.y, 0.2f);
#pragma unroll
        for (int sh = 16; sh >= 1; sh >>= 1)
            p += __shfl_xor_sync(0xffffffffu, p, sh);
        float mn = fmaxf(m, p);
        float sc = __expf(m - mn);
        float w  = __expf(p - mn);
        dn = dn * sc + w;
        acc.x = acc.x * sc + a.x * w;
        acc.y = acc.y * sc + a.y * w;
        m = mn;
    }

    float inv = 1.f / dn;
    float2 bi = *(const float2*)(bias2 + lane * 2);
    float v0 = lrelu(acc.x * inv + bi.x, 0.01f);
    float v1 = lrelu(acc.y * inv + bi.y, 0.01f);

    int g = batch[d];
    atomicAdd(&g_pool[g * 64 + lane * 2 + 0], v0);
    atomicAdd(&g_pool[g * 64 + lane * 2 + 1], v1);
    if (lane == 0) atomicAdd(&g_cnt[g], 1.f);
}

// ---------------- MLP head: mean, fc1+leaky, fc2 ----------------
__global__ void k_head(const float* __restrict__ fc1_w, const float* __restrict__ fc1_b,
                       const float* __restrict__ fc2_w, const float* __restrict__ fc2_b,
                       float* __restrict__ out) {
    __shared__ float p[64], q[64];
    int g = blockIdx.x, t = threadIdx.x;
    float cnt = fmaxf(g_cnt[g], 1.f);
    if (t < 64) p[t] = g_pool[g * 64 + t] / cnt;
    __syncthreads();
    if (t < 64) {
        float acc = fc1_b[t];
#pragma unroll
        for (int k = 0; k < 64; k++) acc += p[k] * fc1_w[t * 64 + k];
        q[t] = lrelu(acc, 0.01f);
    }
    __syncthreads();
    for (int o = t; o < 768; o += blockDim.x) {
        float acc = fc2_b[o];
#pragma unroll
        for (int k = 0; k < 64; k++) acc += q[k] * fc2_w[o * 64 + k];
        out[g * 768 + o] = acc;
    }
}

// ---------------- launch ----------------
extern "C" void kernel_launch(void* const* d_in, const int* in_sizes, int n_in,
                              void* d_out, int out_size) {
    const float* x     = (const float*)d_in[0];
    const int*   ei    = (const int*)d_in[1];
    const int*   batch = (const int*)d_in[2];
    const float* w1_l = (const float*)d_in[3];
    const float* b1_l = (const float*)d_in[4];
    const float* w1_r = (const float*)d_in[5];
    const float* b1_r = (const float*)d_in[6];
    const float* att1 = (const float*)d_in[7];
    const float* bias1 = (const float*)d_in[8];
    const float* w2_l = (const float*)d_in[9];
    const float* b2_l = (const float*)d_in[10];
    const float* w2_r = (const float*)d_in[11];
    const float* b2_r = (const float*)d_in[12];
    const float* att2 = (const float*)d_in[13];
    const float* bias2 = (const float*)d_in[14];
    const float* fc1_w = (const float*)d_in[15];
    const float* fc1_b = (const float*)d_in[16];
    const float* fc2_w = (const float*)d_in[17];
    const float* fc2_b = (const float*)d_in[18];
    float* out = (float*)d_out;

    // CSR build
    k_init<<<(NN + 255) / 256, 256>>>();
    k_deg<<<(ETOT + 255) / 256, 256>>>(ei);
    k_scan<<<1, 1024>>>();
    k_scatter<<<(ETOT + 255) / 256, 256>>>(ei);

    // layer 1
    k_gemm1<<<(NN + 31) / 32, 256>>>(x, w1_l, b1_l, w1_r, b1_r);
    k_attn1<<<(NN * 32 + 255) / 256, 256>>>(att1, bias1);

    // layer 2
    k_gemm2<<<(NN + 31) / 32, 256>>>(w2_l, b2_l, w2_r, b2_r);
    k_attn2<<<(NN * 32 + 255) / 256, 256>>>(att2, bias2, batch);

    // head
    k_head<<<GG, 256>>>(fc1_w, fc1_b, fc2_w, fc2_b, out);
}

// round 9
// speedup vs baseline: 2.0315x; 1.0369x over previous
#include <cuda_runtime.h>
#include <mma.h>
using namespace nvcuda;

#define NN   50000
#define EE   800000
#define ETOT 850000
#define GG   256

// ---------------- scratch (device globals; no allocation allowed) ----------------
__device__ float g_xl1[NN * 128];
__device__ float g_xr1[NN * 128];
__device__ float g_out1[NN * 128];

__device__ float g_xl2[NN * 64];
__device__ float g_xr2[NN * 64];

__device__ float g_pool[GG * 64];
__device__ float g_cnt[GG];

__device__ int g_deg[NN];
__device__ int g_row[NN + 1];
__device__ int g_cursor[NN];
__device__ int g_csrc[ETOT];

__device__ __forceinline__ float lrelu(float v, float s) { return v > 0.f ? v : v * s; }

// ---------------- init: zero histogram + pool ----------------
__global__ void k_init() {
    int i = blockIdx.x * blockDim.x + threadIdx.x;
    if (i < NN) g_deg[i] = 0;
    if (i < GG * 64) g_pool[i] = 0.f;
    if (i < GG) g_cnt[i] = 0.f;
}

// ---------------- CSR build: histogram ----------------
__global__ void k_deg(const int* __restrict__ ei) {
    int e = blockIdx.x * blockDim.x + threadIdx.x;
    if (e >= ETOT) return;
    int d = (e < EE) ? ei[EE + e] : (e - EE);
    atomicAdd(&g_deg[d], 1);
}

// ---------------- CSR build: single-block exclusive scan over 50k ----------------
__global__ void k_scan() {
    __shared__ int ssum[1024];
    int t = threadIdx.x;
    const int CH = (NN + 1023) / 1024; // 49
    int lo = t * CH, hi = min(lo + CH, NN);
    int s = 0;
    for (int i = lo; i < hi; i++) s += g_deg[i];
    ssum[t] = s;
    __syncthreads();
    for (int off = 1; off < 1024; off <<= 1) {
        int v = 0;
        if (t >= off) v = ssum[t - off];
        __syncthreads();
        if (t >= off) ssum[t] += v;
        __syncthreads();
    }
    int run = (t == 0) ? 0 : ssum[t - 1];
    for (int i = lo; i < hi; i++) {
        g_row[i] = run;
        g_cursor[i] = run;
        run += g_deg[i];
    }
    if (t == 0) g_row[NN] = ETOT;
}

// ---------------- CSR build: scatter src by dst ----------------
__global__ void k_scatter(const int* __restrict__ ei) {
    int e = blockIdx.x * blockDim.x + threadIdx.x;
    if (e >= ETOT) return;
    int s, d;
    if (e < EE) { s = ei[e]; d = ei[EE + e]; }
    else        { s = d = e - EE; }
    int pos = atomicAdd(&g_cursor[d], 1);
    g_csrc[pos] = s;
}

// ---------------- layer-1 node transforms via tf32 wmma ----------------
__global__ void k_gemm1(const float* __restrict__ x,
                        const float* __restrict__ wl, const float* __restrict__ bl,
                        const float* __restrict__ wr, const float* __restrict__ br) {
    __shared__ float sa[32 * 136];
    __shared__ float st[8 * 256];
    int tid = threadIdx.x;
    int wid = tid >> 5, lane = tid & 31;
    int node0 = blockIdx.x * 32;

    for (int i = tid; i < 1024; i += 256) {
        int f = i * 4;
        int r = f >> 7, c = f & 127;
        int n = node0 + r;
        float4 v = (n < NN) ? *(const float4*)(x + (size_t)n * 128 + c)
                            : make_float4(0.f, 0.f, 0.f, 0.f);
        *(float4*)(sa + r * 136 + c) = v;
    }
    __syncthreads();

    int wm = wid >> 2;
    int wn = wid & 3;
    const float* wbase = (wn < 2) ? wl : wr;
    int ncol0 = (wn & 1) * 64;

    wmma::fragment<wmma::accumulator, 16, 16, 8, float> acc[4];
#pragma unroll
    for (int i = 0; i < 4; i++) wmma::fill_fragment(acc[i], 0.f);

#pragma unroll
    for (int k = 0; k < 128; k += 8) {
        wmma::fragment<wmma::matrix_a, 16, 16, 8, wmma::precision::tf32, wmma::row_major> af;
        wmma::load_matrix_sync(af, sa + wm * 16 * 136 + k, 136);
#pragma unroll
        for (int i = 0; i < af.num_elements; i++) af.x[i] = wmma::__float_to_tf32(af.x[i]);
#pragma unroll
        for (int fi = 0; fi < 4; fi++) {
            wmma::fragment<wmma::matrix_b, 16, 16, 8, wmma::precision::tf32, wmma::col_major> bf;
            wmma::load_matrix_sync(bf, wbase + (size_t)(ncol0 + fi * 16) * 128 + k, 128);
#pragma unroll
            for (int i = 0; i < bf.num_elements; i++) bf.x[i] = wmma::__float_to_tf32(bf.x[i]);
            wmma::mma_sync(acc[fi], af, bf, acc[fi]);
        }
    }

    float* stw = st + wid * 256;
#pragma unroll
    for (int fi = 0; fi < 4; fi++) {
        wmma::store_matrix_sync(stw, acc[fi], 16, wmma::mem_row_major);
        __syncwarp();
        int ch = wn * 64 + fi * 16;
        const float* bias = (ch < 128) ? bl : br;
        float* outb = (ch < 128) ? g_xl1 : g_xr1;
        int chl = ch & 127;
        for (int e = lane; e < 256; e += 32) {
            int r = e >> 4, c = e & 15;
            int n = node0 + wm * 16 + r;
            if (n < NN) outb[(size_t)n * 128 + chl + c] = stw[e] + bias[chl + c];
        }
        __syncwarp();
    }
}

// ---------------- layer-1 fused attention: 4x-unrolled online softmax ----------------
__global__ void k_attn1(const float* __restrict__ att, const float* __restrict__ bias1) {
    int d = (blockIdx.x * blockDim.x + threadIdx.x) >> 5;
    if (d >= NN) return;
    int lane = threadIdx.x & 31;

    float4 b  = *(const float4*)(g_xr1 + (size_t)d * 128 + lane * 4);
    float4 wa = *(const float4*)(att + lane * 4);

    int rs = g_row[d], re = g_row[d + 1];
    float m = __int_as_float(0xff800000);
    float dn = 0.f;
    float4 acc = make_float4(0.f, 0.f, 0.f, 0.f);

    int pos = rs;
    for (; pos + 4 <= re; pos += 4) {
        int s0 = g_csrc[pos], s1 = g_csrc[pos + 1], s2 = g_csrc[pos + 2], s3 = g_csrc[pos + 3];
        float4 a0 = *(const float4*)(g_xl1 + (size_t)s0 * 128 + lane * 4);
        float4 a1 = *(const float4*)(g_xl1 + (size_t)s1 * 128 + lane * 4);
        float4 a2 = *(const float4*)(g_xl1 + (size_t)s2 * 128 + lane * 4);
        float4 a3 = *(const float4*)(g_xl1 + (size_t)s3 * 128 + lane * 4);

        float p0 = wa.x * lrelu(a0.x + b.x, 0.2f) + wa.y * lrelu(a0.y + b.y, 0.2f)
                 + wa.z * lrelu(a0.z + b.z, 0.2f) + wa.w * lrelu(a0.w + b.w, 0.2f);
        float p1 = wa.x * lrelu(a1.x + b.x, 0.2f) + wa.y * lrelu(a1.y + b.y, 0.2f)
                 + wa.z * lrelu(a1.z + b.z, 0.2f) + wa.w * lrelu(a1.w + b.w, 0.2f);
        float p2 = wa.x * lrelu(a2.x + b.x, 0.2f) + wa.y * lrelu(a2.y + b.y, 0.2f)
                 + wa.z * lrelu(a2.z + b.z, 0.2f) + wa.w * lrelu(a2.w + b.w, 0.2f);
        float p3 = wa.x * lrelu(a3.x + b.x, 0.2f) + wa.y * lrelu(a3.y + b.y, 0.2f)
                 + wa.z * lrelu(a3.z + b.z, 0.2f) + wa.w * lrelu(a3.w + b.w, 0.2f);

#pragma unroll
        for (int sh = 8; sh >= 1; sh >>= 1) {
            p0 += __shfl_xor_sync(0xffffffffu, p0, sh, 16);
            p1 += __shfl_xor_sync(0xffffffffu, p1, sh, 16);
            p2 += __shfl_xor_sync(0xffffffffu, p2, sh, 16);
            p3 += __shfl_xor_sync(0xffffffffu, p3, sh, 16);
        }

        float mn = fmaxf(fmaxf(m, p0), fmaxf(fmaxf(p1, p2), p3));
        float sc = __expf(m - mn);
        float w0 = __expf(p0 - mn), w1 = __expf(p1 - mn);
        float w2 = __expf(p2 - mn), w3 = __expf(p3 - mn);
        dn = dn * sc + (w0 + w1) + (w2 + w3);
        acc.x = acc.x * sc + a0.x * w0 + a1.x * w1 + a2.x * w2 + a3.x * w3;
        acc.y = acc.y * sc + a0.y * w0 + a1.y * w1 + a2.y * w2 + a3.y * w3;
        acc.z = acc.z * sc + a0.z * w0 + a1.z * w1 + a2.z * w2 + a3.z * w3;
        acc.w = acc.w * sc + a0.w * w0 + a1.w * w1 + a2.w * w2 + a3.w * w3;
        m = mn;
    }
    for (; pos < re; pos++) {
        int s = g_csrc[pos];
        float4 a = *(const float4*)(g_xl1 + (size_t)s * 128 + lane * 4);
        float p = wa.x * lrelu(a.x + b.x, 0.2f) + wa.y * lrelu(a.y + b.y, 0.2f)
                + wa.z * lrelu(a.z + b.z, 0.2f) + wa.w * lrelu(a.w + b.w, 0.2f);
#pragma unroll
        for (int sh = 8; sh >= 1; sh >>= 1)
            p += __shfl_xor_sync(0xffffffffu, p, sh, 16);
        float mn = fmaxf(m, p);
        float sc = __expf(m - mn);
        float w  = __expf(p - mn);
        dn = dn * sc + w;
        acc.x = acc.x * sc + a.x * w;
        acc.y = acc.y * sc + a.y * w;
        acc.z = acc.z * sc + a.z * w;
        acc.w = acc.w * sc + a.w * w;
        m = mn;
    }

    float inv = 1.f / dn;
    float4 bi = *(const float4*)(bias1 + lane * 4);
    float4 o;
    o.x = lrelu(acc.x * inv + bi.x, 0.01f);
    o.y = lrelu(acc.y * inv + bi.y, 0.01f);
    o.z = lrelu(acc.z * inv + bi.z, 0.01f);
    o.w = lrelu(acc.w * inv + bi.w, 0.01f);
    *(float4*)(g_out1 + (size_t)d * 128 + lane * 4) = o;
}

// ---------------- layer-2 node transforms via tf32 wmma ----------------
__global__ void k_gemm2(const float* __restrict__ wl, const float* __restrict__ bl,
                        const float* __restrict__ wr, const float* __restrict__ br) {
    __shared__ float sa[32 * 136];
    __shared__ float st[8 * 256];
    int tid = threadIdx.x;
    int wid = tid >> 5, lane = tid & 31;
    int node0 = blockIdx.x * 32;

    for (int i = tid; i < 1024; i += 256) {
        int f = i * 4;
        int r = f >> 7, c = f & 127;
        int n = node0 + r;
        float4 v = (n < NN) ? *(const float4*)(g_out1 + (size_t)n * 128 + c)
                            : make_float4(0.f, 0.f, 0.f, 0.f);
        *(float4*)(sa + r * 136 + c) = v;
    }
    __syncthreads();

    int wm = wid >> 2;
    int wn = wid & 3;
    const float* wbase = (wn < 2) ? wl : wr;
    int ncol0 = (wn & 1) * 32;

    wmma::fragment<wmma::accumulator, 16, 16, 8, float> acc[2];
#pragma unroll
    for (int i = 0; i < 2; i++) wmma::fill_fragment(acc[i], 0.f);

#pragma unroll
    for (int k = 0; k < 128; k += 8) {
        wmma::fragment<wmma::matrix_a, 16, 16, 8, wmma::precision::tf32, wmma::row_major> af;
        wmma::load_matrix_sync(af, sa + wm * 16 * 136 + k, 136);
#pragma unroll
        for (int i = 0; i < af.num_elements; i++) af.x[i] = wmma::__float_to_tf32(af.x[i]);
#pragma unroll
        for (int fi = 0; fi < 2; fi++) {
            wmma::fragment<wmma::matrix_b, 16, 16, 8, wmma::precision::tf32, wmma::col_major> bf;
            wmma::load_matrix_sync(bf, wbase + (size_t)(ncol0 + fi * 16) * 128 + k, 128);
#pragma unroll
            for (int i = 0; i < bf.num_elements; i++) bf.x[i] = wmma::__float_to_tf32(bf.x[i]);
            wmma::mma_sync(acc[fi], af, bf, acc[fi]);
        }
    }

    float* stw = st + wid * 256;
#pragma unroll
    for (int fi = 0; fi < 2; fi++) {
        wmma::store_matrix_sync(stw, acc[fi], 16, wmma::mem_row_major);
        __syncwarp();
        int ch = wn * 32 + fi * 16;
        const float* bias = (ch < 64) ? bl : br;
        float* outb = (ch < 64) ? g_xl2 : g_xr2;
        int chl = ch & 63;
        for (int e = lane; e < 256; e += 32) {
            int r = e >> 4, c = e & 15;
            int n = node0 + wm * 16 + r;
            if (n < NN) outb[(size_t)n * 64 + chl + c] = stw[e] + bias[chl + c];
        }
        __syncwarp();
    }
}

// ---------------- layer-2 fused attention: 4x-unrolled + mean-pool ----------------
__global__ void k_attn2(const float* __restrict__ att, const float* __restrict__ bias2,
                        const int* __restrict__ batch) {
    int d = (blockIdx.x * blockDim.x + threadIdx.x) >> 5;
    if (d >= NN) return;
    int lane = threadIdx.x & 31;

    float2 b  = *(const float2*)(g_xr2 + (size_t)d * 64 + lane * 2);
    float2 wa = *(const float2*)(att + lane * 2);

    int rs = g_row[d], re = g_row[d + 1];
    float m = __int_as_float(0xff800000);
    float dn = 0.f;
    float2 acc = make_float2(0.f, 0.f);

    int pos = rs;
    for (; pos + 4 <= re; pos += 4) {
        int s0 = g_csrc[pos], s1 = g_csrc[pos + 1], s2 = g_csrc[pos + 2], s3 = g_csrc[pos + 3];
        float2 a0 = *(const float2*)(g_xl2 + (size_t)s0 * 64 + lane * 2);
        float2 a1 = *(const float2*)(g_xl2 + (size_t)s1 * 64 + lane * 2);
        float2 a2 = *(const float2*)(g_xl2 + (size_t)s2 * 64 + lane * 2);
        float2 a3 = *(const float2*)(g_xl2 + (size_t)s3 * 64 + lane * 2);

        float p0 = wa.x * lrelu(a0.x + b.x, 0.2f) + wa.y * lrelu(a0.y + b.y, 0.2f);
        float p1 = wa.x * lrelu(a1.x + b.x, 0.2f) + wa.y * lrelu(a1.y + b.y, 0.2f);
        float p2 = wa.x * lrelu(a2.x + b.x, 0.2f) + wa.y * lrelu(a2.y + b.y, 0.2f);
        float p3 = wa.x * lrelu(a3.x + b.x, 0.2f) + wa.y * lrelu(a3.y + b.y, 0.2f);

#pragma unroll
        for (int sh = 16; sh >= 1; sh >>= 1) {
            p0 += __shfl_xor_sync(0xffffffffu, p0, sh);
            p1 += __shfl_xor_sync(0xffffffffu, p1, sh);
            p2 += __shfl_xor_sync(0xffffffffu, p2, sh);
            p3 += __shfl_xor_sync(0xffffffffu, p3, sh);
        }

        float mn = fmaxf(fmaxf(m, p0), fmaxf(fmaxf(p1, p2), p3));
        float sc = __expf(m - mn);
        float w0 = __expf(p0 - mn), w1 = __expf(p1 - mn);
        float w2 = __expf(p2 - mn), w3 = __expf(p3 - mn);
        dn = dn * sc + (w0 + w1) + (w2 + w3);
        acc.x = acc.x * sc + a0.x * w0 + a1.x * w1 + a2.x * w2 + a3.x * w3;
        acc.y = acc.y * sc + a0.y * w0 + a1.y * w1 + a2.y * w2 + a3.y * w3;
        m = mn;
    }
    for (; pos < re; pos++) {
        int s = g_csrc[pos];
        float2 a = *(const float2*)(g_xl2 + (size_t)s * 64 + lane * 2);
        float p = wa.x * lrelu(a.x + b.x, 0.2f) + wa.y * lrelu(a.y + b.y, 0.2f);
#pragma unroll
        for (int sh = 16; sh >= 1; sh >>= 1)
            p += __shfl_xor_sync(0xffffffffu, p, sh);
        float mn = fmaxf(m, p);
        float sc = __expf(m - mn);
        float w  = __expf(p - mn);
        dn = dn * sc + w;
        acc.x = acc.x * sc + a.x * w;
        acc.y = acc.y * sc + a.y * w;
        m = mn;
    }

    float inv = 1.f / dn;
    float2 bi = *(const float2*)(bias2 + lane * 2);
    float v0 = lrelu(acc.x * inv + bi.x, 0.01f);
    float v1 = lrelu(acc.y * inv + bi.y, 0.01f);

    int g = batch[d];
    atomicAdd(&g_pool[g * 64 + lane * 2 + 0], v0);
    atomicAdd(&g_pool[g * 64 + lane * 2 + 1], v1);
    if (lane == 0) atomicAdd(&g_cnt[g], 1.f);
}

// ---------------- MLP head: mean, fc1+leaky, fc2 ----------------
__global__ void k_head(const float* __restrict__ fc1_w, const float* __restrict__ fc1_b,
                       const float* __restrict__ fc2_w, const float* __restrict__ fc2_b,
                       float* __restrict__ out) {
    __shared__ float p[64], q[64];
    int g = blockIdx.x, t = threadIdx.x;
    float cnt = fmaxf(g_cnt[g], 1.f);
    if (t < 64) p[t] = g_pool[g * 64 + t] / cnt;
    __syncthreads();
    if (t < 64) {
        float acc = fc1_b[t];
#pragma unroll
        for (int k = 0; k < 64; k++) acc += p[k] * fc1_w[t * 64 + k];
        q[t] = lrelu(acc, 0.01f);
    }
    __syncthreads();
    for (int o = t; o < 768; o += blockDim.x) {
        float acc = fc2_b[o];
#pragma unroll
        for (int k = 0; k < 64; k++) acc += q[k] * fc2_w[o * 64 + k];
        out[g * 768 + o] = acc;
    }
}

// ---------------- launch ----------------
extern "C" void kernel_launch(void* const* d_in, const int* in_sizes, int n_in,
                              void* d_out, int out_size) {
    const float* x     = (const float*)d_in[0];
    const int*   ei    = (const int*)d_in[1];
    const int*   batch = (const int*)d_in[2];
    const float* w1_l = (const float*)d_in[3];
    const float* b1_l = (const float*)d_in[4];
    const float* w1_r = (const float*)d_in[5];
    const float* b1_r = (const float*)d_in[6];
    const float* att1 = (const float*)d_in[7];
    const float* bias1 = (const float*)d_in[8];
    const float* w2_l = (const float*)d_in[9];
    const float* b2_l = (const float*)d_in[10];
    const float* w2_r = (const float*)d_in[11];
    const float* b2_r = (const float*)d_in[12];
    const float* att2 = (const float*)d_in[13];
    const float* bias2 = (const float*)d_in[14];
    const float* fc1_w = (const float*)d_in[15];
    const float* fc1_b = (const float*)d_in[16];
    const float* fc2_w = (const float*)d_in[17];
    const float* fc2_b = (const float*)d_in[18];
    float* out = (float*)d_out;

    // one-time host-side stream/event objects (no device memory involved;
    // the captured GPU work is identical on every call)
    static cudaStream_t s_side = nullptr;
    static cudaEvent_t ev_fork = nullptr, ev_join = nullptr;
    if (s_side == nullptr) {
        cudaStreamCreateWithFlags(&s_side, cudaStreamNonBlocking);
        cudaEventCreateWithFlags(&ev_fork, cudaEventDisableTiming);
        cudaEventCreateWithFlags(&ev_join, cudaEventDisableTiming);
    }

    // ---- fork: CSR build on side stream, gemm1 on main stream ----
    cudaEventRecord(ev_fork, 0);
    cudaStreamWaitEvent(s_side, ev_fork, 0);

    k_init<<<(NN + 255) / 256, 256, 0, s_side>>>();
    k_deg<<<(ETOT + 255) / 256, 256, 0, s_side>>>(ei);
    k_scan<<<1, 1024, 0, s_side>>>();
    k_scatter<<<(ETOT + 255) / 256, 256, 0, s_side>>>(ei);
    cudaEventRecord(ev_join, s_side);

    k_gemm1<<<(NN + 31) / 32, 256>>>(x, w1_l, b1_l, w1_r, b1_r);

    // ---- join: attention needs both CSR and gemm1 ----
    cudaStreamWaitEvent(0, ev_join, 0);

    k_attn1<<<(NN * 32 + 255) / 256, 256>>>(att1, bias1);

    // layer 2
    k_gemm2<<<(NN + 31) / 32, 256>>>(w2_l, b2_l, w2_r, b2_r);
    k_attn2<<<(NN * 32 + 255) / 256, 256>>>(att2, bias2, batch);

    // head
    k_head<<<GG, 256>>>(fc1_w, fc1_b, fc2_w, fc2_b, out);
}